// round 2
// baseline (speedup 1.0000x reference)
#include <cuda_runtime.h>
#include <math.h>

#define BATCH 16
#define NHEAD 8
#define HDIM 128
#define BSZ 16
#define SEQL 4096
#define MAXB 384
#define HID 1024
#define NTOK 4097          // 4080 window + 16 partial block + 1 new token
#define NSPLIT 32
#define TPS 129            // ceil(4097/32)
#define KSPLIT 16
#define GEMM_KB 64         // 1024 / 16
#define SCALE 0.08838834764831845f

// ---------------- scratch (device globals: no allocation allowed) ----------
__device__ float g_part_acc[BATCH * NSPLIT * NHEAD * HDIM]; // 2 MB
__device__ float g_part_m[BATCH * NSPLIT * NHEAD];
__device__ float g_part_l[BATCH * NSPLIT * NHEAD];
__device__ float g_attn[BATCH * HID];
__device__ float g_gemm_part[KSPLIT * BATCH * HID];         // 1 MB
__device__ float g_cosT[SEQL * 64];                          // 1 MB
__device__ float g_sinT[SEQL * 64];                          // 1 MB
__device__ int2  g_rowpos[BATCH * NTOK];                     // row, pos

__device__ __forceinline__ float4 ldg4(const float* p) {
    return *reinterpret_cast<const float4*>(p);
}

// ---------------------------------------------------------------------------
// Setup 1: RoPE cos/sin table for all positions 0..4095, 64 freqs.
// One accurate sincosf per thread, whole-chip parallel. grid=1024, block=256.
// ---------------------------------------------------------------------------
__global__ __launch_bounds__(256) void rope_table_kernel()
{
    const int idx = blockIdx.x * 256 + threadIdx.x;  // p*64 + f
    const int p = idx >> 6;
    const int f = idx & 63;
    float invf = (float)(1.0 / pow(10000.0, (double)f / 64.0));
    float ang = (float)p * invf;
    float sv, cv;
    sincosf(ang, &sv, &cv);
    g_cosT[idx] = cv;
    g_sinT[idx] = sv;
}

// ---------------------------------------------------------------------------
// Setup 2: per-(batch, token) physical row + rope position.
// row = -1 -> masked token, row = -2 -> new token (from q/k/v inputs).
// grid = BATCH, block = 256.
// ---------------------------------------------------------------------------
__global__ __launch_bounds__(256) void rowpos_kernel(
    const int* __restrict__ bt, const int* __restrict__ sl)
{
    const int b = blockIdx.x;
    const int num_past = sl[b] - 1;
    const int mblk = num_past >> 4;
    const int rem = num_past & 15;
    const int* btb = bt + b * MAXB;

    for (int t = threadIdx.x; t < NTOK; t += 256) {
        int row, p;
        if (t < 16) {
            row = btb[0] * BSZ + t;
            p = t;
        } else if (t < 4080) {
            int blk = btb[mblk - 254 + ((t - 16) >> 4)];
            row = blk * BSZ + ((t - 16) & 15);
            p = t + 15 - rem;
        } else if (t < 4096) {
            int off = t - 4080;
            row = (off < rem) ? (btb[mblk] * BSZ + off) : -1;
            p = t - 1 - rem;
        } else {
            row = -2;
            p = 4095;
        }
        g_rowpos[b * NTOK + t] = make_int2(row, p);
    }
}

// ---------------------------------------------------------------------------
// Kernel A: split-token online-softmax attention partials.
// grid = (NSPLIT, BATCH, 2), block = 128 (warp w == head hg*4+w)
// No shared memory, no syncthreads: warps fully independent.
// ---------------------------------------------------------------------------
__global__ __launch_bounds__(128) void attn_partial_kernel(
    const float* __restrict__ q, const float* __restrict__ k,
    const float* __restrict__ v, const float* __restrict__ kc,
    const float* __restrict__ vc)
{
    const int b = blockIdx.y;
    const int s = blockIdx.x;
    const int tid = threadIdx.x;
    const int warp = tid >> 5;
    const int lane = tid & 31;
    const int h = blockIdx.z * 4 + warp;

    const int fl = (lane & 15) * 4;
    const bool lo = lane < 16;

    // --- rope q at pos 4095 from table ---
    float4 c4 = ldg4(g_cosT + 4095 * 64 + fl);
    float4 s4 = ldg4(g_sinT + 4095 * 64 + fl);
    float qc[4] = {c4.x, c4.y, c4.z, c4.w};
    float qs[4] = {s4.x, s4.y, s4.z, s4.w};
    float4 qv4 = ldg4(q + b * HID + h * HDIM + lane * 4);
    float qa[4] = {qv4.x, qv4.y, qv4.z, qv4.w};
    float qr[4];
#pragma unroll
    for (int j = 0; j < 4; j++) {
        float qp = __shfl_xor_sync(0xffffffffu, qa[j], 16);
        qr[j] = lo ? qa[j] * qc[j] - qp * qs[j]
                   : qa[j] * qc[j] + qp * qs[j];
    }

    float mval = -INFINITY, lsum = 0.0f;
    float acc[4] = {0.f, 0.f, 0.f, 0.f};

    const int tstart = s * TPS;
    const int tend = min(tstart + TPS, NTOK);
    const int tmax = tend - 1;

    for (int t0 = tstart; t0 < tend; t0 += 4) {
        float ka[4][4], va[4][4], cc[4][4], ssv[4][4];
        bool ok[4];
        // ---- issue all loads for 4 tokens up front (MLP ~16) ----
#pragma unroll
        for (int i = 0; i < 4; i++) {
            int t = t0 + i;
            bool inr = (t < tend);
            int tc = inr ? t : tmax;
            int2 rp = g_rowpos[b * NTOK + tc];
            int row = rp.x;
            int p = rp.y;
            ok[i] = inr && (row != -1);
            const float* kb_;
            const float* vb_;
            if (row == -2) {
                kb_ = k + b * HID;
                vb_ = v + b * HID;
            } else {
                long ro = (long)max(row, 0) * HID;
                kb_ = kc + ro;
                vb_ = vc + ro;
            }
            float4 kv4 = ldg4(kb_ + h * HDIM + lane * 4);
            float4 vv4 = ldg4(vb_ + h * HDIM + lane * 4);
            float4 c4i = ldg4(g_cosT + p * 64 + fl);
            float4 s4i = ldg4(g_sinT + p * 64 + fl);
            ka[i][0] = kv4.x; ka[i][1] = kv4.y; ka[i][2] = kv4.z; ka[i][3] = kv4.w;
            va[i][0] = vv4.x; va[i][1] = vv4.y; va[i][2] = vv4.z; va[i][3] = vv4.w;
            cc[i][0] = c4i.x; cc[i][1] = c4i.y; cc[i][2] = c4i.z; cc[i][3] = c4i.w;
            ssv[i][0] = s4i.x; ssv[i][1] = s4i.y; ssv[i][2] = s4i.z; ssv[i][3] = s4i.w;
        }

        // ---- 4 independent dot products (pipelined shuffles) ----
        float dot[4];
#pragma unroll
        for (int i = 0; i < 4; i++) {
            float d = 0.0f;
#pragma unroll
            for (int j = 0; j < 4; j++) {
                float kp = __shfl_xor_sync(0xffffffffu, ka[i][j], 16);
                float kr = lo ? ka[i][j] * cc[i][j] - kp * ssv[i][j]
                              : ka[i][j] * cc[i][j] + kp * ssv[i][j];
                d += qr[j] * kr;
            }
            dot[i] = d;
        }
#pragma unroll
        for (int o = 16; o > 0; o >>= 1) {
#pragma unroll
            for (int i = 0; i < 4; i++)
                dot[i] += __shfl_xor_sync(0xffffffffu, dot[i], o);
        }

        // ---- amortized online-softmax update for 4 tokens ----
        float sc[4];
#pragma unroll
        for (int i = 0; i < 4; i++)
            sc[i] = ok[i] ? dot[i] * SCALE : -INFINITY;
        float gm = fmaxf(fmaxf(sc[0], sc[1]), fmaxf(sc[2], sc[3]));
        float mn = fmaxf(mval, gm);
        if (mn > -INFINITY) {
            float corr = __expf(mval - mn);
            float w[4];
#pragma unroll
            for (int i = 0; i < 4; i++) w[i] = __expf(sc[i] - mn);
            lsum = lsum * corr + (w[0] + w[1]) + (w[2] + w[3]);
#pragma unroll
            for (int j = 0; j < 4; j++) {
                float a = acc[j] * corr;
                a = fmaf(w[0], va[0][j], a);
                a = fmaf(w[1], va[1][j], a);
                a = fmaf(w[2], va[2][j], a);
                a = fmaf(w[3], va[3][j], a);
                acc[j] = a;
            }
            mval = mn;
        }
    }

    const int idx = (b * NSPLIT + s) * NHEAD + h;
    float* pa = g_part_acc + (long)idx * HDIM + lane * 4;
    pa[0] = acc[0]; pa[1] = acc[1]; pa[2] = acc[2]; pa[3] = acc[3];
    if (lane == 0) {
        g_part_m[idx] = mval;
        g_part_l[idx] = lsum;
    }
}

// ---------------------------------------------------------------------------
// Kernel B: combine the NSPLIT softmax partials.  grid = B*H, block = 128 (d)
// ---------------------------------------------------------------------------
__global__ __launch_bounds__(128) void attn_reduce_kernel()
{
    const int bh = blockIdx.x;
    const int b = bh >> 3;
    const int h = bh & 7;
    const int d = threadIdx.x;

    float M = -INFINITY;
#pragma unroll
    for (int s = 0; s < NSPLIT; s++)
        M = fmaxf(M, g_part_m[(b * NSPLIT + s) * NHEAD + h]);

    float num = 0.0f, den = 0.0f;
    for (int s = 0; s < NSPLIT; s++) {
        int idx = (b * NSPLIT + s) * NHEAD + h;
        float sc = __expf(g_part_m[idx] - M);
        num += g_part_acc[(long)idx * HDIM + d] * sc;
        den += g_part_l[idx] * sc;
    }
    g_attn[b * HID + h * HDIM + d] = num / den;
}

// ---------------------------------------------------------------------------
// Kernel C: split-K GEMM partials: out_part[kb][b][j] = sum_k a[b][k] W[k][j]
// grid = (8 colblocks, KSPLIT), block = 128 (one column each)
// ---------------------------------------------------------------------------
__global__ __launch_bounds__(128) void gemm_partial_kernel(const float* __restrict__ W)
{
    __shared__ float aS[BATCH][GEMM_KB];
    const int cb = blockIdx.x;
    const int kb = blockIdx.y;
    const int j = cb * 128 + threadIdx.x;
    const int k0 = kb * GEMM_KB;

    for (int e = threadIdx.x; e < BATCH * GEMM_KB; e += 128) {
        int bb = e / GEMM_KB;
        int kk = e % GEMM_KB;
        aS[bb][kk] = g_attn[bb * HID + k0 + kk];
    }
    __syncthreads();

    float accb[BATCH];
#pragma unroll
    for (int bb = 0; bb < BATCH; bb++) accb[bb] = 0.0f;

    for (int kk = 0; kk < GEMM_KB; kk++) {
        float w = W[(long)(k0 + kk) * HID + j];
#pragma unroll
        for (int bb = 0; bb < BATCH; bb++)
            accb[bb] = fmaf(aS[bb][kk], w, accb[bb]);
    }
#pragma unroll
    for (int bb = 0; bb < BATCH; bb++)
        g_gemm_part[(kb * BATCH + bb) * HID + j] = accb[bb];
}

// ---------------------------------------------------------------------------
// Kernel D: sum k-split partials (float4). grid = 32, block = 128 -> 4096 f4
// ---------------------------------------------------------------------------
__global__ __launch_bounds__(128) void gemm_final_kernel(float* __restrict__ out)
{
    const int idx = blockIdx.x * 128 + threadIdx.x;  // over 4096 float4s
    float4 sum = make_float4(0.f, 0.f, 0.f, 0.f);
#pragma unroll
    for (int kb = 0; kb < KSPLIT; kb++) {
        float4 p = ldg4(g_gemm_part + (long)kb * BATCH * HID + idx * 4);
        sum.x += p.x; sum.y += p.y; sum.z += p.z; sum.w += p.w;
    }
    reinterpret_cast<float4*>(out)[idx] = sum;
}

// ---------------------------------------------------------------------------
extern "C" void kernel_launch(void* const* d_in, const int* in_sizes, int n_in,
                              void* d_out, int out_size)
{
    const float* q  = (const float*)d_in[0];
    const float* k  = (const float*)d_in[1];
    const float* v  = (const float*)d_in[2];
    // d_in[3] = positions (unused; equals seq_lens - 1)
    const float* kc = (const float*)d_in[4];
    const float* vc = (const float*)d_in[5];
    const int* bt   = (const int*)d_in[6];
    const int* sl   = (const int*)d_in[7];
    const float* Wo = (const float*)d_in[8];
    float* out = (float*)d_out;

    rope_table_kernel<<<1024, 256>>>();
    rowpos_kernel<<<BATCH, 256>>>(bt, sl);
    attn_partial_kernel<<<dim3(NSPLIT, BATCH, 2), 128>>>(q, k, v, kc, vc);
    attn_reduce_kernel<<<BATCH * NHEAD, 128>>>();
    gemm_partial_kernel<<<dim3(8, KSPLIT), 128>>>(Wo);
    gemm_final_kernel<<<32, 128>>>(out);
}

// round 3
// speedup vs baseline: 1.0343x; 1.0343x over previous
#include <cuda_runtime.h>
#include <math.h>

#define BATCH 16
#define NHEAD 8
#define HDIM 128
#define BSZ 16
#define SEQL 4096
#define MAXB 384
#define HID 1024
#define NTOK 4097          // 16 sink + 4064 window + 16 partial block + 1 new
#define NSPLIT 32
#define TPS 129            // ceil(4097/32)
#define KSPLIT 16
#define GEMM_KB 64
#define CHUNK 8
#define SCALE 0.08838834764831845f

// ---------------- scratch (device globals: no allocation allowed) ----------
__device__ float g_part_acc[BATCH * NSPLIT * NHEAD * HDIM]; // 2 MB
__device__ float g_part_m[BATCH * NSPLIT * NHEAD];
__device__ float g_part_l[BATCH * NSPLIT * NHEAD];
__device__ float g_attn[BATCH * HID];
__device__ float g_gemm_part[KSPLIT * BATCH * HID];         // 1 MB
__device__ float g_ropeT[SEQL * 128];   // per pos: [0:64) cos, [64:128) sin
__device__ int2  g_rowpos[BATCH * NTOK];

__device__ __forceinline__ float4 ldg4(const float* p) {
    return *reinterpret_cast<const float4*>(p);
}
__device__ __forceinline__ float4 ldcs4(const float* p) {
    return __ldcs(reinterpret_cast<const float4*>(p));
}

// ---------------------------------------------------------------------------
// Setup 1: RoPE cos/sin table, positions 0..4095 x 64 freqs. grid=1024x256.
// ---------------------------------------------------------------------------
__global__ __launch_bounds__(256) void rope_table_kernel()
{
    const int idx = blockIdx.x * 256 + threadIdx.x;  // p*64 + f
    const int p = idx >> 6;
    const int f = idx & 63;
    float invf = (float)(1.0 / pow(10000.0, (double)f / 64.0));
    float sv, cv;
    sincosf((float)p * invf, &sv, &cv);
    g_ropeT[p * 128 + f] = cv;
    g_ropeT[p * 128 + 64 + f] = sv;
}

// ---------------------------------------------------------------------------
// Setup 2: per-(batch,token) physical row + rope position.
// row = -1 masked, row = -2 new token. grid=BATCH, block=256.
// ---------------------------------------------------------------------------
__global__ __launch_bounds__(256) void rowpos_kernel(
    const int* __restrict__ bt, const int* __restrict__ sl)
{
    const int b = blockIdx.x;
    const int num_past = sl[b] - 1;
    const int mblk = num_past >> 4;
    const int rem = num_past & 15;
    const int* btb = bt + b * MAXB;

    for (int t = threadIdx.x; t < NTOK; t += 256) {
        int row, p;
        if (t < 16) {
            row = btb[0] * BSZ + t;
            p = t;
        } else if (t < 4080) {
            int blk = btb[mblk - 254 + ((t - 16) >> 4)];
            row = blk * BSZ + ((t - 16) & 15);
            p = t + 15 - rem;
        } else if (t < 4096) {
            int off = t - 4080;
            row = (off < rem) ? (btb[mblk] * BSZ + off) : -1;
            p = t - 1 - rem;
        } else {
            row = -2;
            p = 4095;
        }
        g_rowpos[b * NTOK + t] = make_int2(row, p);
    }
}

// ---------------------------------------------------------------------------
// Kernel A: split-token online-softmax attention partials.
// grid = (NSPLIT, BATCH), block = 256 (warp == head). Double-buffered smem
// stages 8 tokens of cos/sin (shared across all 8 heads) per chunk.
// ---------------------------------------------------------------------------
__global__ __launch_bounds__(256) void attn_partial_kernel(
    const float* __restrict__ q, const float* __restrict__ k,
    const float* __restrict__ v, const float* __restrict__ kc,
    const float* __restrict__ vc)
{
    __shared__ float sbuf[2][CHUNK][128];
    __shared__ int srow[2][CHUNK];

    const int b = blockIdx.y;
    const int s = blockIdx.x;
    const int tid = threadIdx.x;
    const int h = tid >> 5;
    const int lane = tid & 31;
    const int fl = (lane & 15) * 4;
    const bool lo = lane < 16;
    const int hoff = h * HDIM + lane * 4;

    const int tstart = s * TPS;
    const int tend = min(tstart + TPS, NTOK);

    // --- rope q at pos 4095 from table ---
    float4 c4 = ldg4(g_ropeT + 4095 * 128 + fl);
    float4 s4 = ldg4(g_ropeT + 4095 * 128 + 64 + fl);
    float qc[4] = {c4.x, c4.y, c4.z, c4.w};
    float qs[4] = {s4.x, s4.y, s4.z, s4.w};
    float4 qv4 = ldg4(q + b * HID + hoff);
    float qa[4] = {qv4.x, qv4.y, qv4.z, qv4.w};
    float qr[4];
#pragma unroll
    for (int j = 0; j < 4; j++) {
        float qp = __shfl_xor_sync(0xffffffffu, qa[j], 16);
        qr[j] = lo ? qa[j] * qc[j] - qp * qs[j]
                   : qa[j] * qc[j] + qp * qs[j];
    }

    // --- stage first chunk (256 threads: ti = tid>>5, c = tid&31) ---
    {
        const int ti = tid >> 5;
        const int c = tid & 31;
        const int t = tstart + ti;
        if (t < tend) {
            int2 rp = g_rowpos[b * NTOK + t];
            float4 rv = ldg4(g_ropeT + rp.y * 128 + c * 4);
            *reinterpret_cast<float4*>(&sbuf[0][ti][c * 4]) = rv;
            if (c == 0) srow[0][ti] = rp.x;
        } else if (c == 0) {
            srow[0][ti] = -1;
        }
    }

    float mval = -INFINITY, lsum = 0.0f;
    float acc[4] = {0.f, 0.f, 0.f, 0.f};
    int cur = 0;

    const float* kq = k + b * HID;
    const float* vq = v + b * HID;

    for (int t0 = tstart; t0 < tend; t0 += CHUNK) {
        __syncthreads();  // staging for this chunk done; prev processing done
        // --- stage next chunk into the other buffer ---
        const int nxt = t0 + CHUNK;
        if (nxt < tend) {
            const int ti = tid >> 5;
            const int c = tid & 31;
            const int t = nxt + ti;
            if (t < tend) {
                int2 rp = g_rowpos[b * NTOK + t];
                float4 rv = ldg4(g_ropeT + rp.y * 128 + c * 4);
                *reinterpret_cast<float4*>(&sbuf[cur ^ 1][ti][c * 4]) = rv;
                if (c == 0) srow[cur ^ 1][ti] = rp.x;
            } else if (c == 0) {
                srow[cur ^ 1][ti] = -1;
            }
        }

        // --- process current chunk: pairs of tokens ---
#pragma unroll
        for (int i = 0; i < CHUNK; i += 2) {
            const int ta = t0 + i;
            const int tb = t0 + i + 1;
            const int rowa = srow[cur][i];
            const int rowb = srow[cur][i + 1];
            const bool oka = (ta < tend) && (rowa != -1);
            const bool okb = (tb < tend) && (rowb != -1);

            const float* kpa = (rowa == -2) ? kq : kc + (long)max(rowa, 0) * HID;
            const float* vpa = (rowa == -2) ? vq : vc + (long)max(rowa, 0) * HID;
            const float* kpb = (rowb == -2) ? kq : kc + (long)max(rowb, 0) * HID;
            const float* vpb = (rowb == -2) ? vq : vc + (long)max(rowb, 0) * HID;

            float4 kva = ldcs4(kpa + hoff);
            float4 vva = ldcs4(vpa + hoff);
            float4 kvb = ldcs4(kpb + hoff);
            float4 vvb = ldcs4(vpb + hoff);
            float4 ca4 = *reinterpret_cast<const float4*>(&sbuf[cur][i][fl]);
            float4 sa4 = *reinterpret_cast<const float4*>(&sbuf[cur][i][64 + fl]);
            float4 cb4 = *reinterpret_cast<const float4*>(&sbuf[cur][i + 1][fl]);
            float4 sb4 = *reinterpret_cast<const float4*>(&sbuf[cur][i + 1][64 + fl]);

            float kaa[4] = {kva.x, kva.y, kva.z, kva.w};
            float kab[4] = {kvb.x, kvb.y, kvb.z, kvb.w};
            float caa[4] = {ca4.x, ca4.y, ca4.z, ca4.w};
            float saa[4] = {sa4.x, sa4.y, sa4.z, sa4.w};
            float cab[4] = {cb4.x, cb4.y, cb4.z, cb4.w};
            float sab[4] = {sb4.x, sb4.y, sb4.z, sb4.w};

            float da = 0.0f, db = 0.0f;
#pragma unroll
            for (int j = 0; j < 4; j++) {
                float kp1 = __shfl_xor_sync(0xffffffffu, kaa[j], 16);
                float kp2 = __shfl_xor_sync(0xffffffffu, kab[j], 16);
                float kr1 = lo ? kaa[j] * caa[j] - kp1 * saa[j]
                               : kaa[j] * caa[j] + kp1 * saa[j];
                float kr2 = lo ? kab[j] * cab[j] - kp2 * sab[j]
                               : kab[j] * cab[j] + kp2 * sab[j];
                da = fmaf(qr[j], kr1, da);
                db = fmaf(qr[j], kr2, db);
            }
#pragma unroll
            for (int o = 16; o > 0; o >>= 1) {
                da += __shfl_xor_sync(0xffffffffu, da, o);
                db += __shfl_xor_sync(0xffffffffu, db, o);
            }

            float sca = oka ? da * SCALE : -INFINITY;
            float scb = okb ? db * SCALE : -INFINITY;
            float mn = fmaxf(mval, fmaxf(sca, scb));
            if (mn > -INFINITY) {
                float corr = __expf(mval - mn);
                float wa = __expf(sca - mn);
                float wb = __expf(scb - mn);
                lsum = lsum * corr + wa + wb;
                float va_[4] = {vva.x, vva.y, vva.z, vva.w};
                float vb_[4] = {vvb.x, vvb.y, vvb.z, vvb.w};
#pragma unroll
                for (int j = 0; j < 4; j++)
                    acc[j] = fmaf(wb, vb_[j], fmaf(wa, va_[j], acc[j] * corr));
                mval = mn;
            }
        }
        cur ^= 1;
    }

    const int idx = (b * NSPLIT + s) * NHEAD + h;
    float* pa = g_part_acc + (long)idx * HDIM + lane * 4;
    pa[0] = acc[0]; pa[1] = acc[1]; pa[2] = acc[2]; pa[3] = acc[3];
    if (lane == 0) {
        g_part_m[idx] = mval;
        g_part_l[idx] = lsum;
    }
}

// ---------------------------------------------------------------------------
// Kernel B: combine NSPLIT softmax partials. grid = B*H, block = 128.
// Fully unrolled -> MLP ~32, no serial latency chain.
// ---------------------------------------------------------------------------
__global__ __launch_bounds__(128) void attn_reduce_kernel()
{
    const int bh = blockIdx.x;
    const int b = bh >> 3;
    const int h = bh & 7;
    const int d = threadIdx.x;
    const int base = b * NSPLIT * NHEAD + h;

    float mv[NSPLIT];
#pragma unroll
    for (int s = 0; s < NSPLIT; s++)
        mv[s] = g_part_m[base + s * NHEAD];
    float M = -INFINITY;
#pragma unroll
    for (int s = 0; s < NSPLIT; s++) M = fmaxf(M, mv[s]);

    float num = 0.0f, den = 0.0f;
#pragma unroll
    for (int s = 0; s < NSPLIT; s++) {
        int idx = base + s * NHEAD;
        float sc = __expf(mv[s] - M);
        num = fmaf(g_part_acc[(long)idx * HDIM + d], sc, num);
        den = fmaf(g_part_l[idx], sc, den);
    }
    g_attn[b * HID + h * HDIM + d] = num / den;
}

// ---------------------------------------------------------------------------
// Kernel C: split-K GEMM partials. grid = (8, KSPLIT), block = 128.
// ---------------------------------------------------------------------------
__global__ __launch_bounds__(128) void gemm_partial_kernel(const float* __restrict__ W)
{
    __shared__ float aS[BATCH][GEMM_KB];
    const int cb = blockIdx.x;
    const int kb = blockIdx.y;
    const int j = cb * 128 + threadIdx.x;
    const int k0 = kb * GEMM_KB;

    for (int e = threadIdx.x; e < BATCH * GEMM_KB; e += 128) {
        int bb = e / GEMM_KB;
        int kk = e % GEMM_KB;
        aS[bb][kk] = g_attn[bb * HID + k0 + kk];
    }
    __syncthreads();

    float accb[BATCH];
#pragma unroll
    for (int bb = 0; bb < BATCH; bb++) accb[bb] = 0.0f;

    for (int kk = 0; kk < GEMM_KB; kk++) {
        float w = W[(long)(k0 + kk) * HID + j];
#pragma unroll
        for (int bb = 0; bb < BATCH; bb++)
            accb[bb] = fmaf(aS[bb][kk], w, accb[bb]);
    }
#pragma unroll
    for (int bb = 0; bb < BATCH; bb++)
        g_gemm_part[(kb * BATCH + bb) * HID + j] = accb[bb];
}

// ---------------------------------------------------------------------------
// Kernel D: sum k-split partials (float4). grid = 32, block = 128.
// ---------------------------------------------------------------------------
__global__ __launch_bounds__(128) void gemm_final_kernel(float* __restrict__ out)
{
    const int idx = blockIdx.x * 128 + threadIdx.x;  // 4096 float4s
    float4 sum = make_float4(0.f, 0.f, 0.f, 0.f);
#pragma unroll
    for (int kb = 0; kb < KSPLIT; kb++) {
        float4 p = ldg4(g_gemm_part + (long)kb * BATCH * HID + idx * 4);
        sum.x += p.x; sum.y += p.y; sum.z += p.z; sum.w += p.w;
    }
    reinterpret_cast<float4*>(out)[idx] = sum;
}

// ---------------------------------------------------------------------------
extern "C" void kernel_launch(void* const* d_in, const int* in_sizes, int n_in,
                              void* d_out, int out_size)
{
    const float* q  = (const float*)d_in[0];
    const float* k  = (const float*)d_in[1];
    const float* v  = (const float*)d_in[2];
    const float* kc = (const float*)d_in[4];
    const float* vc = (const float*)d_in[5];
    const int* bt   = (const int*)d_in[6];
    const int* sl   = (const int*)d_in[7];
    const float* Wo = (const float*)d_in[8];
    float* out = (float*)d_out;

    rope_table_kernel<<<1024, 256>>>();
    rowpos_kernel<<<BATCH, 256>>>(bt, sl);
    attn_partial_kernel<<<dim3(NSPLIT, BATCH), 256>>>(q, k, v, kc, vc);
    attn_reduce_kernel<<<BATCH * NHEAD, 128>>>();
    gemm_partial_kernel<<<dim3(8, KSPLIT), 128>>>(Wo);
    gemm_final_kernel<<<32, 128>>>(out);
}

// round 4
// speedup vs baseline: 1.4405x; 1.3928x over previous
#include <cuda_runtime.h>
#include <math.h>

#define BATCH 16
#define NHEAD 8
#define HDIM 128
#define BSZ 16
#define SEQL 4096
#define MAXB 384
#define HID 1024
#define NTOK 4097          // 16 sink + 4064 window + 16 partial block + 1 new
#define NSPLIT 64
#define TPS 68             // 64*68 = 4352 >= 4097, multiple of 4
#define NTOKP 4352
#define KSPLIT 16
#define GEMM_KB 64
#define CHUNK 8
#define SCALE 0.08838834764831845f

// ---------------- scratch (device globals: no allocation allowed) ----------
__device__ float g_part_acc[BATCH * NSPLIT * NHEAD * HDIM]; // 4 MB
__device__ float g_scores[BATCH * NHEAD * NTOKP];           // 2.2 MB
__device__ float g_attn[BATCH * HID];
__device__ float g_gemm_part[KSPLIT * BATCH * HID];         // 1 MB
__device__ float g_ropeT[SEQL * 128];   // per pos: [0:64) cos, [64:128) sin
__device__ float g_invf[64];
__device__ int2  g_rowpos[BATCH * NTOK];

__device__ __forceinline__ float4 ldg4(const float* p) {
    return *reinterpret_cast<const float4*>(p);
}
__device__ __forceinline__ float2 ldg2(const float* p) {
    return *reinterpret_cast<const float2*>(p);
}

// ---------------------------------------------------------------------------
// Setup 1: rowpos + (block 0) the 64 inv-freqs via double pow (only 64 calls).
// ---------------------------------------------------------------------------
__global__ __launch_bounds__(256) void rowpos_kernel(
    const int* __restrict__ bt, const int* __restrict__ sl)
{
    const int b = blockIdx.x;
    if (b == 0 && threadIdx.x < 64)
        g_invf[threadIdx.x] =
            (float)(1.0 / pow(10000.0, (double)threadIdx.x / 64.0));

    const int num_past = sl[b] - 1;
    const int mblk = num_past >> 4;
    const int rem = num_past & 15;
    const int* btb = bt + b * MAXB;

    for (int t = threadIdx.x; t < NTOK; t += 256) {
        int row, p;
        if (t < 16) {
            row = btb[0] * BSZ + t;
            p = t;
        } else if (t < 4080) {
            int blk = btb[mblk - 254 + ((t - 16) >> 4)];
            row = blk * BSZ + ((t - 16) & 15);
            p = t + 15 - rem;
        } else if (t < 4096) {
            int off = t - 4080;
            row = (off < rem) ? (btb[mblk] * BSZ + off) : -1;
            p = t - 1 - rem;
        } else {
            row = -2;
            p = 4095;
        }
        g_rowpos[b * NTOK + t] = make_int2(row, p);
    }
}

// ---------------------------------------------------------------------------
// Setup 2: RoPE cos/sin table (pure fp32 sincosf). grid=2048, block=128.
// ---------------------------------------------------------------------------
__global__ __launch_bounds__(128) void rope_table_kernel()
{
    const int idx = blockIdx.x * 128 + threadIdx.x;  // p*64 + f
    const int p = idx >> 6;
    const int f = idx & 63;
    float sv, cv;
    sincosf((float)p * g_invf[f], &sv, &cv);
    g_ropeT[p * 128 + f] = cv;
    g_ropeT[p * 128 + 64 + f] = sv;
}

// ---------------------------------------------------------------------------
// Kernel 1: scores[b][h][t] = dot(rope(q), rope(K_t)) * SCALE.
// grid = (NSPLIT, BATCH), block = 256 (warp == head).
// Lane L owns dims {2L, 2L+1, 2L+64, 2L+65}: rope fully in-lane, no shuffles
// except the final reduction tree. No cross-token dependencies -> deep MLP.
// ---------------------------------------------------------------------------
__global__ __launch_bounds__(256) void score_kernel(
    const float* __restrict__ q, const float* __restrict__ k,
    const float* __restrict__ kc)
{
    __shared__ float sbuf[2][CHUNK][128];
    __shared__ int srow[2][CHUNK];

    const int b = blockIdx.y;
    const int s = blockIdx.x;
    const int tid = threadIdx.x;
    const int h = tid >> 5;
    const int lane = tid & 31;
    const int d2 = lane * 2;

    const int tstart = s * TPS;
    const int tend = min(tstart + TPS, NTOK);
    if (tstart >= NTOK) return;

    // --- rope q at pos 4095 (in-lane pairs) ---
    float2 qx = ldg2(q + b * HID + h * HDIM + d2);
    float2 qy = ldg2(q + b * HID + h * HDIM + 64 + d2);
    float2 c0 = ldg2(g_ropeT + 4095 * 128 + d2);
    float2 s0 = ldg2(g_ropeT + 4095 * 128 + 64 + d2);
    float qlo0 = qx.x * c0.x - qy.x * s0.x;
    float qlo1 = qx.y * c0.y - qy.y * s0.y;
    float qhi0 = qy.x * c0.x + qx.x * s0.x;
    float qhi1 = qy.y * c0.y + qx.y * s0.y;

    // --- stage first chunk: thread e -> token e>>5, float4 col (e&31)*4 ---
    {
        const int ti = tid >> 5;
        const int c = tid & 31;
        const int t = tstart + ti;
        if (t < tend) {
            int2 rp = g_rowpos[b * NTOK + t];
            *reinterpret_cast<float4*>(&sbuf[0][ti][c * 4]) =
                ldg4(g_ropeT + rp.y * 128 + c * 4);
            if (c == 0) srow[0][ti] = rp.x;
        } else if (c == 0) {
            srow[0][ti] = -1;
        }
    }

    const float* kq = k + b * HID;
    const int hb = h * HDIM;
    const long sbase = (long)(b * NHEAD + h) * NTOKP;
    int cur = 0;

    for (int t0 = tstart; t0 < tend; t0 += CHUNK) {
        __syncthreads();
        const int nxt = t0 + CHUNK;
        if (nxt < tend) {
            const int ti = tid >> 5;
            const int c = tid & 31;
            const int t = nxt + ti;
            if (t < tend) {
                int2 rp = g_rowpos[b * NTOK + t];
                *reinterpret_cast<float4*>(&sbuf[cur ^ 1][ti][c * 4]) =
                    ldg4(g_ropeT + rp.y * 128 + c * 4);
                if (c == 0) srow[cur ^ 1][ti] = rp.x;
            } else if (c == 0) {
                srow[cur ^ 1][ti] = -1;
            }
        }

#pragma unroll
        for (int g = 0; g < CHUNK; g += 4) {
            const int tg = t0 + g;
            if (tg >= tend) break;
            float dot[4];
            bool ok[4];
#pragma unroll
            for (int i = 0; i < 4; i++) {
                const int t = tg + i;
                const int row = srow[cur][g + i];
                ok[i] = (t < tend) && (row != -1);
                const float* kp = (row == -2) ? kq
                                 : kc + (long)max(row, 0) * HID;
                float2 kx = ldg2(kp + hb + d2);
                float2 ky = ldg2(kp + hb + 64 + d2);
                float2 cc = *reinterpret_cast<const float2*>(&sbuf[cur][g + i][d2]);
                float2 ss = *reinterpret_cast<const float2*>(&sbuf[cur][g + i][64 + d2]);
                float klo0 = kx.x * cc.x - ky.x * ss.x;
                float klo1 = kx.y * cc.y - ky.y * ss.y;
                float khi0 = ky.x * cc.x + kx.x * ss.x;
                float khi1 = ky.y * cc.y + kx.y * ss.y;
                float d = qlo0 * klo0;
                d = fmaf(qlo1, klo1, d);
                d = fmaf(qhi0, khi0, d);
                d = fmaf(qhi1, khi1, d);
                dot[i] = d;
            }
#pragma unroll
            for (int o = 16; o > 0; o >>= 1) {
#pragma unroll
                for (int i = 0; i < 4; i++)
                    dot[i] += __shfl_xor_sync(0xffffffffu, dot[i], o);
            }
            if (lane == 0) {
                float4 sc;
                sc.x = ok[0] ? dot[0] * SCALE : -INFINITY;
                sc.y = ok[1] ? dot[1] * SCALE : -INFINITY;
                sc.z = ok[2] ? dot[2] * SCALE : -INFINITY;
                sc.w = ok[3] ? dot[3] * SCALE : -INFINITY;
                *reinterpret_cast<float4*>(&g_scores[sbase + tg]) = sc;
            }
        }
        cur ^= 1;
    }
}

// ---------------------------------------------------------------------------
// Kernel 2: per (b,h) softmax over scores -> normalized weights in place.
// grid = 128, block = 256. Each thread caches its 17 scores in registers.
// ---------------------------------------------------------------------------
__global__ __launch_bounds__(256) void softmax_kernel()
{
    __shared__ float red[8];
    const int bh = blockIdx.x;
    const int tid = threadIdx.x;
    const int lane = tid & 31;
    const int warp = tid >> 5;
    float* sc = g_scores + (long)bh * NTOKP;

    float v[17];
    float M = -INFINITY;
#pragma unroll
    for (int r = 0; r < 17; r++) {
        int t = tid + r * 256;
        v[r] = (t < NTOK) ? sc[t] : -INFINITY;
        M = fmaxf(M, v[r]);
    }
#pragma unroll
    for (int o = 16; o > 0; o >>= 1)
        M = fmaxf(M, __shfl_xor_sync(0xffffffffu, M, o));
    if (lane == 0) red[warp] = M;
    __syncthreads();
    M = red[lane & 7];
#pragma unroll
    for (int o = 4; o > 0; o >>= 1)
        M = fmaxf(M, __shfl_xor_sync(0xffffffffu, M, o));

    float sum = 0.0f;
#pragma unroll
    for (int r = 0; r < 17; r++) {
        v[r] = __expf(v[r] - M);   // exp(-inf - M) = 0
        sum += v[r];
    }
#pragma unroll
    for (int o = 16; o > 0; o >>= 1)
        sum += __shfl_xor_sync(0xffffffffu, sum, o);
    __syncthreads();
    if (lane == 0) red[warp] = sum;
    __syncthreads();
    sum = red[lane & 7];
#pragma unroll
    for (int o = 4; o > 0; o >>= 1)
        sum += __shfl_xor_sync(0xffffffffu, sum, o);
    const float inv = __frcp_rn(sum);

#pragma unroll
    for (int r = 0; r < 17; r++) {
        int t = tid + r * 256;
        sc[t] = (t < NTOK) ? v[r] * inv : 0.0f;
    }
}

// ---------------------------------------------------------------------------
// Kernel 3: partial acc[b][s][h][:] = sum_t w[t] * V_t. Pure streaming FMA.
// grid = (NSPLIT, BATCH), block = 256 (warp == head). No smem, no syncs.
// ---------------------------------------------------------------------------
__global__ __launch_bounds__(256) void wv_kernel(
    const float* __restrict__ v, const float* __restrict__ vc)
{
    const int b = blockIdx.y;
    const int s = blockIdx.x;
    const int tid = threadIdx.x;
    const int h = tid >> 5;
    const int lane = tid & 31;
    const int hoff = h * HDIM + lane * 4;

    const int tstart = s * TPS;
    const int tend = min(tstart + TPS, NTOK);
    const float* vq = v + b * HID;
    const float* wrow = g_scores + (long)(b * NHEAD + h) * NTOKP;

    float acc[4] = {0.f, 0.f, 0.f, 0.f};

    for (int t0 = tstart; t0 < tend; t0 += 4) {
        float4 w4 = ldg4(wrow + t0);   // broadcast across warp
        float wv[4] = {w4.x, w4.y, w4.z, w4.w};
        float4 vv[4];
#pragma unroll
        for (int i = 0; i < 4; i++) {
            int t = min(t0 + i, NTOK - 1);
            int row = g_rowpos[b * NTOK + t].x;
            const float* vp = (row == -2) ? vq
                             : vc + (long)max(row, 0) * HID;
            vv[i] = ldg4(vp + hoff);
        }
#pragma unroll
        for (int j = 0; j < 4; j++) {
            float* a = &acc[j];
            const float e0 = j == 0 ? 0.f : 0.f; (void)e0;
            float x = *a;
            x = fmaf(wv[0], (&vv[0].x)[j], x);
            x = fmaf(wv[1], (&vv[1].x)[j], x);
            x = fmaf(wv[2], (&vv[2].x)[j], x);
            x = fmaf(wv[3], (&vv[3].x)[j], x);
            *a = x;
        }
    }

    float* pa = g_part_acc +
        (long)((b * NSPLIT + s) * NHEAD + h) * HDIM + lane * 4;
    pa[0] = acc[0]; pa[1] = acc[1]; pa[2] = acc[2]; pa[3] = acc[3];
}

// ---------------------------------------------------------------------------
// Kernel 4: sum the 64 split partials (weights already normalized).
// grid = 128 (b,h), block = 128 (d). Fully unrolled -> MLP 64.
// ---------------------------------------------------------------------------
__global__ __launch_bounds__(128) void reduce_kernel()
{
    const int bh = blockIdx.x;
    const int b = bh >> 3;
    const int h = bh & 7;
    const int d = threadIdx.x;
    const float* base = g_part_acc + (long)(b * NSPLIT * NHEAD + h) * HDIM + d;

    float sum = 0.0f;
#pragma unroll
    for (int s = 0; s < NSPLIT; s++)
        sum += base[(long)s * NHEAD * HDIM];
    g_attn[b * HID + h * HDIM + d] = sum;
}

// ---------------------------------------------------------------------------
// Kernel 5: split-K GEMM partials. grid = (8, KSPLIT), block = 128.
// ---------------------------------------------------------------------------
__global__ __launch_bounds__(128) void gemm_partial_kernel(const float* __restrict__ W)
{
    __shared__ float aS[BATCH][GEMM_KB];
    const int cb = blockIdx.x;
    const int kb = blockIdx.y;
    const int j = cb * 128 + threadIdx.x;
    const int k0 = kb * GEMM_KB;

    for (int e = threadIdx.x; e < BATCH * GEMM_KB; e += 128) {
        int bb = e / GEMM_KB;
        int kk = e % GEMM_KB;
        aS[bb][kk] = g_attn[bb * HID + k0 + kk];
    }
    __syncthreads();

    float accb[BATCH];
#pragma unroll
    for (int bb = 0; bb < BATCH; bb++) accb[bb] = 0.0f;

    for (int kk = 0; kk < GEMM_KB; kk++) {
        float w = W[(long)(k0 + kk) * HID + j];
#pragma unroll
        for (int bb = 0; bb < BATCH; bb++)
            accb[bb] = fmaf(aS[bb][kk], w, accb[bb]);
    }
#pragma unroll
    for (int bb = 0; bb < BATCH; bb++)
        g_gemm_part[(kb * BATCH + bb) * HID + j] = accb[bb];
}

// ---------------------------------------------------------------------------
// Kernel 6: sum k-split partials (float4). grid = 32, block = 128.
// ---------------------------------------------------------------------------
__global__ __launch_bounds__(128) void gemm_final_kernel(float* __restrict__ out)
{
    const int idx = blockIdx.x * 128 + threadIdx.x;  // 4096 float4s
    float4 sum = make_float4(0.f, 0.f, 0.f, 0.f);
#pragma unroll
    for (int kb = 0; kb < KSPLIT; kb++) {
        float4 p = ldg4(g_gemm_part + (long)kb * BATCH * HID + idx * 4);
        sum.x += p.x; sum.y += p.y; sum.z += p.z; sum.w += p.w;
    }
    reinterpret_cast<float4*>(out)[idx] = sum;
}

// ---------------------------------------------------------------------------
extern "C" void kernel_launch(void* const* d_in, const int* in_sizes, int n_in,
                              void* d_out, int out_size)
{
    const float* q  = (const float*)d_in[0];
    const float* k  = (const float*)d_in[1];
    const float* v  = (const float*)d_in[2];
    const float* kc = (const float*)d_in[4];
    const float* vc = (const float*)d_in[5];
    const int* bt   = (const int*)d_in[6];
    const int* sl   = (const int*)d_in[7];
    const float* Wo = (const float*)d_in[8];
    float* out = (float*)d_out;

    rowpos_kernel<<<BATCH, 256>>>(bt, sl);
    rope_table_kernel<<<2048, 128>>>();
    score_kernel<<<dim3(NSPLIT, BATCH), 256>>>(q, k, kc);
    softmax_kernel<<<BATCH * NHEAD, 256>>>();
    wv_kernel<<<dim3(NSPLIT, BATCH), 256>>>(v, vc);
    reduce_kernel<<<BATCH * NHEAD, 128>>>();
    gemm_partial_kernel<<<dim3(8, KSPLIT), 128>>>(Wo);
    gemm_final_kernel<<<32, 128>>>(out);
}

// round 6
// speedup vs baseline: 1.4588x; 1.0127x over previous
#include <cuda_runtime.h>
#include <math.h>

#define BATCH 16
#define NHEAD 8
#define HDIM 128
#define BSZ 16
#define SEQL 4096
#define MAXB 384
#define HID 1024
#define NTOK 4097          // 16 sink + 4064 window + 16 partial block + 1 new
#define NSPLIT 64
#define TPS 72             // MULTIPLE OF 8; splits 0..56 cover 4097 tokens
#define NTOKP 4352
#define KSPLIT 16
#define GEMM_KB 64
#define CHUNK 8
#define SCALE 0.08838834764831845f

// ---------------- scratch (device globals: no allocation allowed) ----------
__device__ float g_part_acc[BATCH * NSPLIT * NHEAD * HDIM]; // 4 MB
__device__ float g_scores[BATCH * NHEAD * NTOKP];           // 2.2 MB
__device__ float g_attn[BATCH * HID];
__device__ float g_gemm_part[KSPLIT * BATCH * HID];         // 1 MB
__device__ float g_ropeT[SEQL * 128];   // per pos: [0:64) cos, [64:128) sin
__device__ float g_invf[64];
__device__ int2  g_rowpos[BATCH * NTOK];

__device__ __forceinline__ float4 ldg4(const float* p) {
    return *reinterpret_cast<const float4*>(p);
}
__device__ __forceinline__ float2 ldg2(const float* p) {
    return *reinterpret_cast<const float2*>(p);
}

// ---------------------------------------------------------------------------
// Setup 1: rowpos + (block 0) 64 inv-freqs via double pow (64 calls total).
// ---------------------------------------------------------------------------
__global__ __launch_bounds__(256) void rowpos_kernel(
    const int* __restrict__ bt, const int* __restrict__ sl)
{
    const int b = blockIdx.x;
    if (b == 0 && threadIdx.x < 64)
        g_invf[threadIdx.x] =
            (float)(1.0 / pow(10000.0, (double)threadIdx.x / 64.0));

    const int num_past = sl[b] - 1;
    const int mblk = num_past >> 4;
    const int rem = num_past & 15;
    const int* btb = bt + b * MAXB;

    for (int t = threadIdx.x; t < NTOK; t += 256) {
        int row, p;
        if (t < 16) {
            row = btb[0] * BSZ + t;
            p = t;
        } else if (t < 4080) {
            int blk = btb[mblk - 254 + ((t - 16) >> 4)];
            row = blk * BSZ + ((t - 16) & 15);
            p = t + 15 - rem;
        } else if (t < 4096) {
            int off = t - 4080;
            row = (off < rem) ? (btb[mblk] * BSZ + off) : -1;
            p = t - 1 - rem;
        } else {
            row = -2;
            p = 4095;
        }
        g_rowpos[b * NTOK + t] = make_int2(row, p);
    }
}

// ---------------------------------------------------------------------------
// Setup 2: RoPE cos/sin table (pure fp32 sincosf). grid=2048, block=128.
// ---------------------------------------------------------------------------
__global__ __launch_bounds__(128) void rope_table_kernel()
{
    const int idx = blockIdx.x * 128 + threadIdx.x;  // p*64 + f
    const int p = idx >> 6;
    const int f = idx & 63;
    float sv, cv;
    sincosf((float)p * g_invf[f], &sv, &cv);
    g_ropeT[p * 128 + f] = cv;
    g_ropeT[p * 128 + 64 + f] = sv;
}

// ---------------------------------------------------------------------------
// Kernel 1: scores[b][h][t] = dot(rope(q), rope(K_t)) * SCALE.
// grid = (NSPLIT, BATCH), block = 256 (warp == head).
// Full 8-token chunk per iteration: 16 K-loads issued up front (MLP 16).
// ---------------------------------------------------------------------------
__global__ __launch_bounds__(256) void score_kernel(
    const float* __restrict__ q, const float* __restrict__ k,
    const float* __restrict__ kc)
{
    __shared__ float sbuf[2][CHUNK][128];
    __shared__ int srow[2][CHUNK];

    const int b = blockIdx.y;
    const int s = blockIdx.x;
    const int tid = threadIdx.x;
    const int h = tid >> 5;
    const int lane = tid & 31;
    const int d2 = lane * 2;

    const int tstart = s * TPS;
    const int tend = min(tstart + TPS, NTOK);
    if (tstart >= NTOK) return;

    // --- rope q at pos 4095 (in-lane pairs) ---
    float2 qx = ldg2(q + b * HID + h * HDIM + d2);
    float2 qy = ldg2(q + b * HID + h * HDIM + 64 + d2);
    float2 c0 = ldg2(g_ropeT + 4095 * 128 + d2);
    float2 s0 = ldg2(g_ropeT + 4095 * 128 + 64 + d2);
    float qlo0 = qx.x * c0.x - qy.x * s0.x;
    float qlo1 = qx.y * c0.y - qy.y * s0.y;
    float qhi0 = qy.x * c0.x + qx.x * s0.x;
    float qhi1 = qy.y * c0.y + qx.y * s0.y;

    // --- stage first chunk: thread e -> token e>>5, float4 col (e&31)*4 ---
    {
        const int ti = tid >> 5;
        const int c = tid & 31;
        const int t = tstart + ti;
        if (t < tend) {
            int2 rp = g_rowpos[b * NTOK + t];
            *reinterpret_cast<float4*>(&sbuf[0][ti][c * 4]) =
                ldg4(g_ropeT + rp.y * 128 + c * 4);
            if (c == 0) srow[0][ti] = rp.x;
        } else if (c == 0) {
            srow[0][ti] = -1;
        }
    }

    const float* kq = k + b * HID;
    const int hb = h * HDIM;
    const long sbase = (long)(b * NHEAD + h) * NTOKP;
    int cur = 0;

    for (int t0 = tstart; t0 < tend; t0 += CHUNK) {
        __syncthreads();
        const int nxt = t0 + CHUNK;
        if (nxt < tend) {
            const int ti = tid >> 5;
            const int c = tid & 31;
            const int t = nxt + ti;
            if (t < tend) {
                int2 rp = g_rowpos[b * NTOK + t];
                *reinterpret_cast<float4*>(&sbuf[cur ^ 1][ti][c * 4]) =
                    ldg4(g_ropeT + rp.y * 128 + c * 4);
                if (c == 0) srow[cur ^ 1][ti] = rp.x;
            } else if (c == 0) {
                srow[cur ^ 1][ti] = -1;
            }
        }

        // ---- issue all 16 K loads for the 8-token chunk ----
        float2 kx[CHUNK], ky[CHUNK];
        bool ok[CHUNK];
#pragma unroll
        for (int i = 0; i < CHUNK; i++) {
            const int t = t0 + i;
            const int row = srow[cur][i];
            ok[i] = (t < tend) && (row != -1);
            const float* kp = (row == -2) ? kq : kc + (long)max(row, 0) * HID;
            kx[i] = ldg2(kp + hb + d2);
            ky[i] = ldg2(kp + hb + 64 + d2);
        }

        // ---- rope + dot for all 8 ----
        float dot[CHUNK];
#pragma unroll
        for (int i = 0; i < CHUNK; i++) {
            float2 cc = *reinterpret_cast<const float2*>(&sbuf[cur][i][d2]);
            float2 ss = *reinterpret_cast<const float2*>(&sbuf[cur][i][64 + d2]);
            float klo0 = kx[i].x * cc.x - ky[i].x * ss.x;
            float klo1 = kx[i].y * cc.y - ky[i].y * ss.y;
            float khi0 = ky[i].x * cc.x + kx[i].x * ss.x;
            float khi1 = ky[i].y * cc.y + kx[i].y * ss.y;
            float d = qlo0 * klo0;
            d = fmaf(qlo1, klo1, d);
            d = fmaf(qhi0, khi0, d);
            d = fmaf(qhi1, khi1, d);
            dot[i] = d;
        }
#pragma unroll
        for (int o = 16; o > 0; o >>= 1) {
#pragma unroll
            for (int i = 0; i < CHUNK; i++)
                dot[i] += __shfl_xor_sync(0xffffffffu, dot[i], o);
        }
        if (lane == 0) {
            float4 sa, sb;
            sa.x = ok[0] ? dot[0] * SCALE : -INFINITY;
            sa.y = ok[1] ? dot[1] * SCALE : -INFINITY;
            sa.z = ok[2] ? dot[2] * SCALE : -INFINITY;
            sa.w = ok[3] ? dot[3] * SCALE : -INFINITY;
            sb.x = ok[4] ? dot[4] * SCALE : -INFINITY;
            sb.y = ok[5] ? dot[5] * SCALE : -INFINITY;
            sb.z = ok[6] ? dot[6] * SCALE : -INFINITY;
            sb.w = ok[7] ? dot[7] * SCALE : -INFINITY;
            *reinterpret_cast<float4*>(&g_scores[sbase + t0]) = sa;
            *reinterpret_cast<float4*>(&g_scores[sbase + t0 + 4]) = sb;
        }
        cur ^= 1;
    }
}

// ---------------------------------------------------------------------------
// Kernel 2: per (b,h) softmax -> normalized weights in place.
// grid = 128, block = 512. 9 tokens per thread in registers.
// Pads [NTOK, NTOKP) with zeros (wv over-reads into the pad).
// ---------------------------------------------------------------------------
__global__ __launch_bounds__(512) void softmax_kernel()
{
    __shared__ float red[16];
    const int bh = blockIdx.x;
    const int tid = threadIdx.x;
    const int lane = tid & 31;
    const int warp = tid >> 5;
    float* sc = g_scores + (long)bh * NTOKP;

    float v[9];
    float M = -INFINITY;
#pragma unroll
    for (int r = 0; r < 9; r++) {
        int t = tid + r * 512;
        v[r] = (t < NTOK) ? sc[t] : -INFINITY;
        M = fmaxf(M, v[r]);
    }
#pragma unroll
    for (int o = 16; o > 0; o >>= 1)
        M = fmaxf(M, __shfl_xor_sync(0xffffffffu, M, o));
    if (lane == 0) red[warp] = M;
    __syncthreads();
    M = red[lane & 15];
#pragma unroll
    for (int o = 8; o > 0; o >>= 1)
        M = fmaxf(M, __shfl_xor_sync(0xffffffffu, M, o));

    float sum = 0.0f;
#pragma unroll
    for (int r = 0; r < 9; r++) {
        v[r] = __expf(v[r] - M);   // exp(-inf - M) = 0
        sum += v[r];
    }
#pragma unroll
    for (int o = 16; o > 0; o >>= 1)
        sum += __shfl_xor_sync(0xffffffffu, sum, o);
    __syncthreads();
    if (lane == 0) red[warp] = sum;
    __syncthreads();
    sum = red[lane & 15];
#pragma unroll
    for (int o = 8; o > 0; o >>= 1)
        sum += __shfl_xor_sync(0xffffffffu, sum, o);
    const float inv = __frcp_rn(sum);

#pragma unroll
    for (int r = 0; r < 9; r++) {
        int t = tid + r * 512;
        if (t < NTOKP)
            sc[t] = (t < NTOK) ? v[r] * inv : 0.0f;
    }
}

// ---------------------------------------------------------------------------
// Kernel 3: partial acc[b][s][h][:] = sum_t w[t] * V_t. 8-token groups.
// grid = (NSPLIT, BATCH), block = 256 (warp == head). No smem, no syncs.
// TPS % 8 == 0 -> groups never cross split boundaries; tail over-reads
// land in the zero pad.
// ---------------------------------------------------------------------------
__global__ __launch_bounds__(256) void wv_kernel(
    const float* __restrict__ v, const float* __restrict__ vc)
{
    const int b = blockIdx.y;
    const int s = blockIdx.x;
    const int tid = threadIdx.x;
    const int h = tid >> 5;
    const int lane = tid & 31;
    const int hoff = h * HDIM + lane * 4;

    const int tstart = s * TPS;
    const int tend = min(tstart + TPS, NTOK);
    float* pa = g_part_acc +
        (long)((b * NSPLIT + s) * NHEAD + h) * HDIM + lane * 4;
    if (tstart >= NTOK) {
        pa[0] = 0.f; pa[1] = 0.f; pa[2] = 0.f; pa[3] = 0.f;
        return;
    }
    const float* vq = v + b * HID;
    const float* wrow = g_scores + (long)(b * NHEAD + h) * NTOKP;

    float acc[4] = {0.f, 0.f, 0.f, 0.f};

    for (int t0 = tstart; t0 < tend; t0 += 8) {
        // pad region weights are zero, safe to over-read on final tail
        float4 w0 = ldg4(wrow + t0);
        float4 w1 = ldg4(wrow + t0 + 4);
        float wv_[8] = {w0.x, w0.y, w0.z, w0.w, w1.x, w1.y, w1.z, w1.w};
        float4 vv[8];
#pragma unroll
        for (int i = 0; i < 8; i++) {
            int t = min(t0 + i, NTOK - 1);
            int row = g_rowpos[b * NTOK + t].x;
            const float* vp = (row == -2) ? vq : vc + (long)max(row, 0) * HID;
            vv[i] = ldg4(vp + hoff);
        }
#pragma unroll
        for (int j = 0; j < 4; j++) {
            float x = acc[j];
#pragma unroll
            for (int i = 0; i < 8; i++)
                x = fmaf(wv_[i], (&vv[i].x)[j], x);
            acc[j] = x;
        }
    }

    pa[0] = acc[0]; pa[1] = acc[1]; pa[2] = acc[2]; pa[3] = acc[3];
}

// ---------------------------------------------------------------------------
// Kernel 4: sum the 64 split partials. grid = 128 (b,h), block = 128 (d).
// ---------------------------------------------------------------------------
__global__ __launch_bounds__(128) void reduce_kernel()
{
    const int bh = blockIdx.x;
    const int b = bh >> 3;
    const int h = bh & 7;
    const int d = threadIdx.x;
    const float* base = g_part_acc + (long)(b * NSPLIT * NHEAD + h) * HDIM + d;

    float sum = 0.0f;
#pragma unroll
    for (int s = 0; s < NSPLIT; s++)
        sum += base[(long)s * NHEAD * HDIM];
    g_attn[b * HID + h * HDIM + d] = sum;
}

// ---------------------------------------------------------------------------
// Kernel 5: split-K GEMM partials. grid = (8, KSPLIT), block = 128.
// ---------------------------------------------------------------------------
__global__ __launch_bounds__(128) void gemm_partial_kernel(const float* __restrict__ W)
{
    __shared__ float aS[BATCH][GEMM_KB];
    const int cb = blockIdx.x;
    const int kb = blockIdx.y;
    const int j = cb * 128 + threadIdx.x;
    const int k0 = kb * GEMM_KB;

    for (int e = threadIdx.x; e < BATCH * GEMM_KB; e += 128) {
        int bb = e / GEMM_KB;
        int kk = e % GEMM_KB;
        aS[bb][kk] = g_attn[bb * HID + k0 + kk];
    }
    __syncthreads();

    float accb[BATCH];
#pragma unroll
    for (int bb = 0; bb < BATCH; bb++) accb[bb] = 0.0f;

    for (int kk = 0; kk < GEMM_KB; kk++) {
        float w = W[(long)(k0 + kk) * HID + j];
#pragma unroll
        for (int bb = 0; bb < BATCH; bb++)
            accb[bb] = fmaf(aS[bb][kk], w, accb[bb]);
    }
#pragma unroll
    for (int bb = 0; bb < BATCH; bb++)
        g_gemm_part[(kb * BATCH + bb) * HID + j] = accb[bb];
}

// ---------------------------------------------------------------------------
// Kernel 6: sum k-split partials (float4). grid = 32, block = 128.
// ---------------------------------------------------------------------------
__global__ __launch_bounds__(128) void gemm_final_kernel(float* __restrict__ out)
{
    const int idx = blockIdx.x * 128 + threadIdx.x;  // 4096 float4s
    float4 sum = make_float4(0.f, 0.f, 0.f, 0.f);
#pragma unroll
    for (int kb = 0; kb < KSPLIT; kb++) {
        float4 p = ldg4(g_gemm_part + (long)kb * BATCH * HID + idx * 4);
        sum.x += p.x; sum.y += p.y; sum.z += p.z; sum.w += p.w;
    }
    reinterpret_cast<float4*>(out)[idx] = sum;
}

// ---------------------------------------------------------------------------
extern "C" void kernel_launch(void* const* d_in, const int* in_sizes, int n_in,
                              void* d_out, int out_size)
{
    const float* q  = (const float*)d_in[0];
    const float* k  = (const float*)d_in[1];
    const float* v  = (const float*)d_in[2];
    const float* kc = (const float*)d_in[4];
    const float* vc = (const float*)d_in[5];
    const int* bt   = (const int*)d_in[6];
    const int* sl   = (const int*)d_in[7];
    const float* Wo = (const float*)d_in[8];
    float* out = (float*)d_out;

    rowpos_kernel<<<BATCH, 256>>>(bt, sl);
    rope_table_kernel<<<2048, 128>>>();
    score_kernel<<<dim3(NSPLIT, BATCH), 256>>>(q, k, kc);
    softmax_kernel<<<BATCH * NHEAD, 512>>>();
    wv_kernel<<<dim3(NSPLIT, BATCH), 256>>>(v, vc);
    reduce_kernel<<<BATCH * NHEAD, 128>>>();
    gemm_partial_kernel<<<dim3(8, KSPLIT), 128>>>(Wo);
    gemm_final_kernel<<<32, 128>>>(out);
}